// round 1
// baseline (speedup 1.0000x reference)
#include <cuda_runtime.h>
#include <cuda_bf16.h>
#include <math.h>

// Problem constants
#define BATCH 4
#define LSEQ  8192
#define CC    256
#define BL    32768            // BATCH*LSEQ
#define HID   2048
#define NSPLIT 16              // n-splits for context GEMM

// ---------------- scratch (device globals; no allocations allowed) -----------
__device__ float g_q   [BL * CC];
__device__ float g_k   [BL * CC];
__device__ float g_v   [BL * CC];
__device__ float g_attn[BL * CC];
__device__ float g_lin [BL * CC];
__device__ float g_ln1 [BL * CC];
__device__ float g_f2  [BL * CC];
__device__ float g_hid [(long long)BL * HID];          // 256 MB
__device__ float g_ctx [BATCH * CC * CC];
__device__ float g_cpart[NSPLIT * BATCH * CC * CC];    // split-N partials
__device__ float g_cm  [BATCH * CC];
__device__ float g_cs  [BATCH * CC];

// ---------------- generic 128x128x8 fp32 SGEMM -------------------------------
// EPI: 0 = none, 1 = +bias, 2 = +bias then exact GELU
// DUAL: A is virtual concat [A (cols 0..255) | A2 (cols 256..511)], lda=256
template<int EPI, bool DUAL>
__global__ __launch_bounds__(256, 2)
void sgemm_k(const float* __restrict__ A, const float* __restrict__ A2, int lda,
             const float* __restrict__ B, const float* __restrict__ bias,
             float* __restrict__ C,
             int M, int N, int K,
             long long sA, long long sB, long long sC)
{
    A += blockIdx.z * sA;
    B += blockIdx.z * sB;
    C += blockIdx.z * sC;

    const int m0 = blockIdx.y * 128;
    const int n0 = blockIdx.x * 128;

    __shared__ float As[8][128];
    __shared__ float Bs[8][128];

    const int t  = threadIdx.x;
    const int tx = t & 15;        // 16 col-groups
    const int ty = t >> 4;        // 16 row-groups

    // global-load mapping
    const int am = t >> 1;              // 0..127
    const int ak = (t & 1) << 2;        // 0 or 4
    const int bk = t >> 5;              // 0..7
    const int bn = (t & 31) << 2;       // 0..124

    float acc[8][8];
#pragma unroll
    for (int i = 0; i < 8; i++)
#pragma unroll
        for (int j = 0; j < 8; j++) acc[i][j] = 0.f;

    for (int k0 = 0; k0 < K; k0 += 8) {
        const float* Aeff;
        int kk0;
        if (DUAL) {
            if (k0 < 256) { Aeff = A;  kk0 = k0; }
            else          { Aeff = A2; kk0 = k0 - 256; }
        } else { Aeff = A; kk0 = k0; }

        float4 av = *(const float4*)&Aeff[(long long)(m0 + am) * lda + kk0 + ak];
        float4 bv = *(const float4*)&B[(long long)(k0 + bk) * N + n0 + bn];

        As[ak + 0][am] = av.x;
        As[ak + 1][am] = av.y;
        As[ak + 2][am] = av.z;
        As[ak + 3][am] = av.w;
        *(float4*)&Bs[bk][bn] = bv;
        __syncthreads();

#pragma unroll
        for (int kk = 0; kk < 8; kk++) {
            float a[8], bb[8];
#pragma unroll
            for (int i = 0; i < 4; i++) {
                a[i]     = As[kk][ty * 4 + i];
                a[i + 4] = As[kk][64 + ty * 4 + i];
            }
#pragma unroll
            for (int j = 0; j < 4; j++) {
                bb[j]     = Bs[kk][tx * 4 + j];
                bb[j + 4] = Bs[kk][64 + tx * 4 + j];
            }
#pragma unroll
            for (int i = 0; i < 8; i++)
#pragma unroll
                for (int j = 0; j < 8; j++)
                    acc[i][j] += a[i] * bb[j];
        }
        __syncthreads();
    }

    // epilogue
#pragma unroll
    for (int i = 0; i < 8; i++) {
        int r = m0 + ((i < 4) ? (ty * 4 + i) : (64 + ty * 4 + (i - 4)));
#pragma unroll
        for (int j = 0; j < 8; j++) {
            int c = n0 + ((j < 4) ? (tx * 4 + j) : (64 + tx * 4 + (j - 4)));
            float v = acc[i][j];
            if (EPI >= 1) v += bias[c];
            if (EPI == 2) v = 0.5f * v * (1.0f + erff(v * 0.70710678118654752f));
            C[(long long)r * N + c] = v;
        }
    }
}

// ---------------- column softmax over L (axis=1) ------------------------------
// pass1: per-(b, channel) online max + sum(exp(x - max))
__global__ void softmax_p1(const float* __restrict__ Kin,
                           float* __restrict__ cm, float* __restrict__ cs)
{
    const int b  = blockIdx.y;
    const int c0 = blockIdx.x * 32;
    const int tx = threadIdx.x;   // 0..31 channel
    const int ty = threadIdx.y;   // 0..15 L partition

    const float* kb = Kin + (long long)b * LSEQ * CC + c0 + tx;
    float m = -1e30f, s = 0.f;
    for (int l = ty; l < LSEQ; l += 16) {
        float v = kb[(long long)l * CC];
        if (v > m) { s = s * expf(m - v) + 1.0f; m = v; }
        else       { s += expf(v - m); }
    }

    __shared__ float Ms[16][32], Ss[16][32];
    Ms[ty][tx] = m; Ss[ty][tx] = s;
    __syncthreads();
    for (int st = 8; st > 0; st >>= 1) {
        if (ty < st) {
            float m2 = Ms[ty + st][tx], s2 = Ss[ty + st][tx];
            float mm = fmaxf(m, m2);
            s = s * expf(m - mm) + s2 * expf(m2 - mm);
            m = mm;
            Ms[ty][tx] = m; Ss[ty][tx] = s;
        }
        __syncthreads();
    }
    if (ty == 0) { cm[b * CC + c0 + tx] = m; cs[b * CC + c0 + tx] = s; }
}

// pass2: in-place normalize
__global__ void softmax_p2(float* __restrict__ Kio,
                           const float* __restrict__ cm, const float* __restrict__ cs)
{
    int idx = blockIdx.x * 256 + threadIdx.x;   // BL*CC = 2^23 elements
    int c = idx & 255;
    int b = idx >> 21;                           // LSEQ*CC = 2^21
    float v = Kio[idx];
    Kio[idx] = expf(v - cm[b * CC + c]) / cs[b * CC + c];
}

// ---------------- context^T: ctxT[b][e][d] = sum_n k[n,e] q[n,d] --------------
// split-N partials (deterministic), 64x64 tile per block
__global__ __launch_bounds__(256)
void ata64(const float* __restrict__ Km, const float* __restrict__ Qm,
           float* __restrict__ part)
{
    const int b     = blockIdx.z;
    const int tile  = blockIdx.x;           // 0..15
    const int split = blockIdx.y;           // 0..NSPLIT-1
    const int e0 = (tile >> 2) * 64;
    const int d0 = (tile & 3)  * 64;

    const float* kb = Km + (long long)b * LSEQ * CC;
    const float* qb = Qm + (long long)b * LSEQ * CC;

    __shared__ float Ks[8][64], Qs[8][64];
    const int t  = threadIdx.x;
    const int tx = t & 15, ty = t >> 4;

    float acc[4][4];
#pragma unroll
    for (int i = 0; i < 4; i++)
#pragma unroll
        for (int j = 0; j < 4; j++) acc[i][j] = 0.f;

    const int nbeg = split * (LSEQ / NSPLIT);
    const int nend = nbeg + (LSEQ / NSPLIT);
    for (int n0 = nbeg; n0 < nend; n0 += 8) {
#pragma unroll
        for (int i = 0; i < 2; i++) {
            int lin = t + i * 256;
            int r = lin >> 6, c = lin & 63;
            Ks[r][c] = kb[(long long)(n0 + r) * CC + e0 + c];
            Qs[r][c] = qb[(long long)(n0 + r) * CC + d0 + c];
        }
        __syncthreads();
#pragma unroll
        for (int r = 0; r < 8; r++) {
            float a[4], bb[4];
#pragma unroll
            for (int i = 0; i < 4; i++) a[i]  = Ks[r][ty * 4 + i];
#pragma unroll
            for (int j = 0; j < 4; j++) bb[j] = Qs[r][tx * 4 + j];
#pragma unroll
            for (int i = 0; i < 4; i++)
#pragma unroll
                for (int j = 0; j < 4; j++) acc[i][j] += a[i] * bb[j];
        }
        __syncthreads();
    }

    float* cp = part + ((long long)(split * BATCH + b) << 16);
#pragma unroll
    for (int i = 0; i < 4; i++)
#pragma unroll
        for (int j = 0; j < 4; j++)
            cp[(e0 + ty * 4 + i) * CC + d0 + tx * 4 + j] = acc[i][j];
}

__global__ void reduce_ctx(const float* __restrict__ part, float* __restrict__ ctx)
{
    int i = blockIdx.x * 256 + threadIdx.x;   // BATCH*CC*CC = 262144
    int b = i >> 16;
    int w = i & 65535;
    float s = 0.f;
#pragma unroll
    for (int sp = 0; sp < NSPLIT; sp++)
        s += part[((long long)(sp * BATCH + b) << 16) + w];
    ctx[i] = s;
}

// ---------------- layernorm over C=256 (optionally + residual) ---------------
template<bool RES>
__global__ void layernorm_k(const float* __restrict__ X,
                            const float* __restrict__ gamma,
                            const float* __restrict__ beta,
                            const float* __restrict__ src,
                            float* __restrict__ O)
{
    const int row = blockIdx.x;
    const int t   = threadIdx.x;   // 256
    const long long base = (long long)row * CC;

    float x = X[base + t];
    __shared__ float red[8];

    float s = x;
#pragma unroll
    for (int o = 16; o; o >>= 1) s += __shfl_xor_sync(0xffffffffu, s, o);
    if ((t & 31) == 0) red[t >> 5] = s;
    __syncthreads();
    float mu = 0.f;
#pragma unroll
    for (int i = 0; i < 8; i++) mu += red[i];
    mu *= (1.0f / 256.0f);
    __syncthreads();

    float d = x - mu;
    float q = d * d;
#pragma unroll
    for (int o = 16; o; o >>= 1) q += __shfl_xor_sync(0xffffffffu, q, o);
    if ((t & 31) == 0) red[t >> 5] = q;
    __syncthreads();
    float var = 0.f;
#pragma unroll
    for (int i = 0; i < 8; i++) var += red[i];
    var *= (1.0f / 256.0f);

    float y = d * rsqrtf(var + 1e-5f) * gamma[t] + beta[t];
    O[base + t] = RES ? (src[base + t] + y) : y;
}

// ---------------- launch ------------------------------------------------------
extern "C" void kernel_launch(void* const* d_in, const int* in_sizes, int n_in,
                              void* d_out, int out_size)
{
    const float* src    = (const float*)d_in[0];
    const float* tgt    = (const float*)d_in[1];
    const float* Wq     = (const float*)d_in[2];
    const float* Wk     = (const float*)d_in[3];
    const float* Wv     = (const float*)d_in[4];
    const float* Wl     = (const float*)d_in[5];
    const float* gamma1 = (const float*)d_in[6];
    const float* beta1  = (const float*)d_in[7];
    const float* W1     = (const float*)d_in[8];
    const float* b1     = (const float*)d_in[9];
    const float* W2     = (const float*)d_in[10];
    const float* b2     = (const float*)d_in[11];
    const float* gamma2 = (const float*)d_in[12];
    const float* beta2  = (const float*)d_in[13];
    float* out = (float*)d_out;

    float *q, *k, *v, *attn, *lin, *ln1, *f2, *hid, *ctx, *cpart, *cm, *cs;
    cudaGetSymbolAddress((void**)&q,     g_q);
    cudaGetSymbolAddress((void**)&k,     g_k);
    cudaGetSymbolAddress((void**)&v,     g_v);
    cudaGetSymbolAddress((void**)&attn,  g_attn);
    cudaGetSymbolAddress((void**)&lin,   g_lin);
    cudaGetSymbolAddress((void**)&ln1,   g_ln1);
    cudaGetSymbolAddress((void**)&f2,    g_f2);
    cudaGetSymbolAddress((void**)&hid,   g_hid);
    cudaGetSymbolAddress((void**)&ctx,   g_ctx);
    cudaGetSymbolAddress((void**)&cpart, g_cpart);
    cudaGetSymbolAddress((void**)&cm,    g_cm);
    cudaGetSymbolAddress((void**)&cs,    g_cs);

    dim3 blk(256);

    // q = source @ Wq ; k = target @ Wk ; v = target @ Wv
    sgemm_k<0, false><<<dim3(2, 256, 1), blk>>>(src, nullptr, CC, Wq, nullptr, q,  BL, CC, CC, 0, 0, 0);
    sgemm_k<0, false><<<dim3(2, 256, 1), blk>>>(tgt, nullptr, CC, Wk, nullptr, k,  BL, CC, CC, 0, 0, 0);
    sgemm_k<0, false><<<dim3(2, 256, 1), blk>>>(tgt, nullptr, CC, Wv, nullptr, v,  BL, CC, CC, 0, 0, 0);

    // softmax over token dim (axis=1), in place on k
    softmax_p1<<<dim3(8, 4), dim3(32, 16)>>>(k, cm, cs);
    softmax_p2<<<32768, 256>>>(k, cm, cs);

    // ctxT[b] = k_soft[b]^T @ q[b]  (split-N partials + deterministic reduce)
    ata64<<<dim3(16, NSPLIT, BATCH), 256>>>(k, q, cpart);
    reduce_ctx<<<1024, 256>>>(cpart, ctx);

    // attn[b] = v[b] @ ctxT[b]   (batched)
    sgemm_k<0, false><<<dim3(2, 64, BATCH), blk>>>(v, nullptr, CC, ctx, nullptr, attn,
                                                   LSEQ, CC, CC,
                                                   (long long)LSEQ * CC, (long long)CC * CC,
                                                   (long long)LSEQ * CC);

    // message = LN(attn @ Wl)
    sgemm_k<0, false><<<dim3(2, 256, 1), blk>>>(attn, nullptr, CC, Wl, nullptr, lin, BL, CC, CC, 0, 0, 0);
    layernorm_k<false><<<32768, 256>>>(lin, gamma1, beta1, nullptr, ln1);

    // hidden = gelu([source | message] @ W1 + b1)   (virtual concat, dual-A)
    sgemm_k<2, true><<<dim3(16, 256, 1), blk>>>(src, ln1, CC, W1, b1, hid, BL, HID, 512, 0, 0, 0);

    // out = source + LN(hidden @ W2 + b2)
    sgemm_k<1, false><<<dim3(2, 256, 1), blk>>>(hid, nullptr, HID, W2, b2, f2, BL, CC, HID, 0, 0, 0);
    layernorm_k<true><<<32768, 256>>>(f2, gamma2, beta2, src, out);
}